// round 7
// baseline (speedup 1.0000x reference)
#include <cuda_runtime.h>
#include <cuda_bf16.h>

// Laplacian-pyramid L1 loss, 5 levels, (32,3,512,512) fp32.
// pyr(in)-pyr(tg) == pyr(in-tg); reflect padding is scale-consistent so the
// upsample needs only a 1-halo down tile. Even/odd column deinterleave keeps
// all smem phases unit-stride. R7: small levels get small tiles (parallelism).

#define BC 96
#define NLVL 5

__device__ __align__(16) float g_scratch[BC * (256*256 + 128*128 + 64*64 + 32*32)];
__device__ double g_sums[NLVL];

__device__ __forceinline__ int refl(int t, int n) {
    if (t < 0)  return -t;
    if (t >= n) return 2*n - 2 - t;
    return t;
}
__device__ __forceinline__ float wt(int i) {
    return (i == 0 || i == 4) ? 1.0f : ((i == 2) ? 6.0f : 4.0f);
}
__device__ __forceinline__ float4 ld4(const float* p) {
    return *reinterpret_cast<const float4*>(p);
}
__device__ __forceinline__ void st4(float* p, float4 v) {
    *reinterpret_cast<float4*>(p) = v;
}
__device__ __forceinline__ float2 ld2(const float* p) {
    return *reinterpret_cast<const float2*>(p);
}
__device__ __forceinline__ void st2(float* p, float2 v) {
    *reinterpret_cast<float2*>(p) = v;
}

__global__ void zero_sums_kernel() {
    if (threadIdx.x < NLVL) g_sums[threadIdx.x] = 0.0;
}

__device__ __forceinline__ void block_reduce_atomic(float v, int lvl, float* sred) {
    const int tid = threadIdx.x;
#pragma unroll
    for (int o = 16; o; o >>= 1) v += __shfl_down_sync(0xffffffffu, v, o);
    if ((tid & 31) == 0) sred[tid >> 5] = v;
    __syncthreads();
    if (tid < 16) {
        float x = (tid < (int)(blockDim.x >> 5)) ? sred[tid] : 0.f;
#pragma unroll
        for (int o = 8; o; o >>= 1) x += __shfl_down_sync(0xffffu, x, o);
        if (tid == 0) atomicAdd(&g_sums[lvl], (double)x);
    }
    __syncthreads();
}

// ---------------- tiled level kernel ----------------
// TILE x TILE region of one bc-plane; deinterleaved smem pipeline.
template <int TILE, int NT, bool DIFF>
__global__ __launch_bounds__(NT)
void lvl_kernel(const float* __restrict__ a, const float* __restrict__ b,
                int srcOff, int dstOff, int H, int lvl, int tilesRow)
{
    constexpr int DT = TILE + 8;          // full-res rows (+4 halo)
    constexpr int DC = DT / 4;            // f4 chunks per full-res row
    constexpr int PE = TILE/2 + 8;        // sdE/sdO pitch (holds DT/2 + read slack)
    constexpr int HT = TILE/2 + 2;        // down rows (+1 halo)
    constexpr int HP = HT + 2;            // st/sdn pitch (mult of 4)
    constexpr int HC = HP / 4;
    constexpr int HI = TILE/2;            // down interior
    constexpr int WC = HI / 4;

    __shared__ float sdE[DT * PE];
    __shared__ float sdO[DT * PE];
    __shared__ float st [DT * HP];        // hgauss temp; later supE/supO
    __shared__ float sdn[HT * HP];
    __shared__ float sred[16];

    const int W = H, h = H >> 1;
    const int tid = threadIdx.x;
    const int ty = blockIdx.x / tilesRow, tx = blockIdx.x - ty * tilesRow;
    const int bc = blockIdx.y;
    const int y0 = ty * TILE, x0 = tx * TILE;
    const int r0 = y0 >> 1,  c0 = x0 >> 1;

    const float* sa = DIFF ? a + (size_t)bc * H * W
                           : g_scratch + srcOff + (size_t)bc * H * W;
    const float* sb = DIFF ? b + (size_t)bc * H * W : nullptr;

    // ---- load diff tile, deinterleave even/odd columns ----
    for (int it = tid; it < DT * DC; it += NT) {
        int row = it / DC, col = it - row * DC;
        int gy  = y0 - 4 + row;
        int gx0 = x0 - 4 + 4 * col;
        float4 v;
        if (gy >= 0 && gy < H && gx0 >= 0 && gx0 + 3 < W) {
            size_t g = (size_t)gy * W + gx0;
            if (DIFF) {
                float4 x1 = __ldcs(reinterpret_cast<const float4*>(sa + g));
                float4 x2 = __ldcs(reinterpret_cast<const float4*>(sb + g));
                v = make_float4(x1.x - x2.x, x1.y - x2.y, x1.z - x2.z, x1.w - x2.w);
            } else {
                v = ld4(sa + g);
            }
        } else {
            int yy = refl(gy, H);
            float t[4];
#pragma unroll
            for (int k = 0; k < 4; k++) {
                int xx = refl(gx0 + k, W);
                size_t g = (size_t)yy * W + xx;
                t[k] = sa[g];
                if (DIFF) t[k] -= sb[g];
            }
            v = make_float4(t[0], t[1], t[2], t[3]);
        }
        st2(sdE + row * PE + 2 * col, make_float2(v.x, v.z));
        st2(sdO + row * PE + 2 * col, make_float2(v.y, v.w));
    }
    __syncthreads();

    // ---- horizontal gauss (stride-2 folded into parity arrays) ----
    for (int it = tid; it < DT * HC; it += NT) {
        int r = it / HC, k = it - (it / HC) * HC;
        const float* Er = sdE + r * PE + 4 * k;
        const float* Or = sdO + r * PE + 4 * k;
        float4 Ea = ld4(Er), Eb = ld4(Er + 4);
        float4 Oa = ld4(Or), Ob = ld4(Or + 4);
        float4 o;
        o.x = Ea.x + 6.f*Ea.y + Ea.z + 4.f*(Oa.x + Oa.y);
        o.y = Ea.y + 6.f*Ea.z + Ea.w + 4.f*(Oa.y + Oa.z);
        o.z = Ea.z + 6.f*Ea.w + Eb.x + 4.f*(Oa.z + Oa.w);
        o.w = Ea.w + 6.f*Eb.x + Eb.y + 4.f*(Oa.w + Ob.x);
        st4(st + r * HP + 4 * k, o);
    }
    __syncthreads();

    // ---- vertical gauss, stride 2 ----
    for (int it = tid; it < HT * HC; it += NT) {
        int r = it / HC, ck = it - r * HC;
        const float* base = st + (2 * r) * HP + 4 * ck;
        float4 r0v = ld4(base),        r1v = ld4(base + HP),
               r2v = ld4(base + 2*HP), r3v = ld4(base + 3*HP),
               r4v = ld4(base + 4*HP);
        float4 o;
        o.x = (r0v.x + 4.f*r1v.x + 6.f*r2v.x + 4.f*r3v.x + r4v.x) * (1.f/256.f);
        o.y = (r0v.y + 4.f*r1v.y + 6.f*r2v.y + 4.f*r3v.y + r4v.y) * (1.f/256.f);
        o.z = (r0v.z + 4.f*r1v.z + 6.f*r2v.z + 4.f*r3v.z + r4v.z) * (1.f/256.f);
        o.w = (r0v.w + 4.f*r1v.w + 6.f*r2v.w + 4.f*r3v.w + r4v.w) * (1.f/256.f);
        st4(sdn + r * HP + 4 * ck, o);
    }
    __syncthreads();

    // ---- write interior down tile (next level source) ----
    {
        float* gdn = g_scratch + dstOff + (size_t)bc * h * h;
        for (int it = tid; it < HI * WC; it += NT) {
            int r = it / WC, ck = it - r * WC;
            const float* s = sdn + (r + 1) * HP + 4 * ck + 1;
            st4(gdn + (size_t)(r0 + r) * h + c0 + 4 * ck,
                make_float4(s[0], s[1], s[2], s[3]));
        }
    }

    // ---- horizontal upsample into parity-split sup ----
    float* supE = st;
    float* supO = st + HT * HI;
    for (int it = tid; it < HT * WC; it += NT) {
        int dr = it / WC, k = it - dr * WC;
        const float* dnr = sdn + dr * HP + 4 * k;
        float4 A = ld4(dnr), B = ld4(dnr + 4);
        float4 e, o;
        e.x = A.x + 6.f*A.y + A.z;  o.x = 4.f*(A.y + A.z);
        e.y = A.y + 6.f*A.z + A.w;  o.y = 4.f*(A.z + A.w);
        e.z = A.z + 6.f*A.w + B.x;  o.z = 4.f*(A.w + B.x);
        e.w = A.w + 6.f*B.x + B.y;  o.w = 4.f*(B.x + B.y);
        st4(supE + dr * HI + 4 * k, e);
        st4(supO + dr * HI + 4 * k, o);
    }
    __syncthreads();

    // ---- vertical upsample + |d - up| (8 px/iter) ----
    float lsum = 0.0f;
    for (int it = tid; it < TILE * WC; it += NT) {
        int y = it / WC, k = it - (it / WC) * WC;
        int lr = (y >> 1) + 1;
        const float* pE = supE + lr * HI + 4 * k;
        const float* pO = supO + lr * HI + 4 * k;
        float4 uE, uO;
        if (y & 1) {
            float4 bE = ld4(pE), cE = ld4(pE + HI);
            float4 bO = ld4(pO), cO = ld4(pO + HI);
            uE.x = 4.f*(bE.x+cE.x); uE.y = 4.f*(bE.y+cE.y);
            uE.z = 4.f*(bE.z+cE.z); uE.w = 4.f*(bE.w+cE.w);
            uO.x = 4.f*(bO.x+cO.x); uO.y = 4.f*(bO.y+cO.y);
            uO.z = 4.f*(bO.z+cO.z); uO.w = 4.f*(bO.w+cO.w);
        } else {
            float4 aE = ld4(pE - HI), bE = ld4(pE), cE = ld4(pE + HI);
            float4 aO = ld4(pO - HI), bO = ld4(pO), cO = ld4(pO + HI);
            uE.x = aE.x + 6.f*bE.x + cE.x; uE.y = aE.y + 6.f*bE.y + cE.y;
            uE.z = aE.z + 6.f*bE.z + cE.z; uE.w = aE.w + 6.f*bE.w + cE.w;
            uO.x = aO.x + 6.f*bO.x + cO.x; uO.y = aO.y + 6.f*bO.y + cO.y;
            uO.z = aO.z + 6.f*bO.z + cO.z; uO.w = aO.w + 6.f*bO.w + cO.w;
        }
        int off = (y + 4) * PE + 4 * k + 2;
        float2 dEa = ld2(sdE + off), dEb = ld2(sdE + off + 2);
        float2 dOa = ld2(sdO + off), dOb = ld2(sdO + off + 2);
        lsum += fabsf(dEa.x - uE.x*(1.f/64.f)) + fabsf(dEa.y - uE.y*(1.f/64.f))
              + fabsf(dEb.x - uE.z*(1.f/64.f)) + fabsf(dEb.y - uE.w*(1.f/64.f))
              + fabsf(dOa.x - uO.x*(1.f/64.f)) + fabsf(dOa.y - uO.y*(1.f/64.f))
              + fabsf(dOb.x - uO.z*(1.f/64.f)) + fabsf(dOb.y - uO.w*(1.f/64.f));
    }
    block_reduce_atomic(lsum, lvl, sred);
}

// ---------------- level 4: whole 32x32 plane per block ----------------
__global__ __launch_bounds__(256)
void lvl4_kernel(int srcOff)
{
    constexpr int H = 32, h = 16, HT2 = 18;
    __shared__ float sa [H * H];
    __shared__ float st [H * HT2];
    __shared__ float sdn[HT2 * HT2];
    __shared__ float sred[16];

    const int tid = threadIdx.x, NT = 256;
    const int bc = blockIdx.x;

    const float* g = g_scratch + srcOff + (size_t)bc * H * H;
    for (int idx = tid; idx < H * H / 4; idx += NT)
        st4(sa + 4*idx, ld4(g + 4*idx));
    __syncthreads();

    for (int idx = tid; idx < H * HT2; idx += NT) {
        int y = idx / HT2, dc = idx - y * HT2;
        const float* row = sa + y * H;
        float acc = 0.f;
#pragma unroll
        for (int j = 0; j < 5; j++) acc += wt(j) * row[refl(2*dc - 4 + j, H)];
        st[idx] = acc;
    }
    __syncthreads();
    for (int idx = tid; idx < HT2 * HT2; idx += NT) {
        int dr = idx / HT2, dc = idx - dr * HT2;
        float acc = 0.f;
#pragma unroll
        for (int i = 0; i < 5; i++) acc += wt(i) * st[refl(2*dr - 4 + i, H) * HT2 + dc];
        sdn[idx] = acc * (1.f/256.f);
    }
    __syncthreads();
    float* sup = st;
    for (int idx = tid; idx < HT2 * H; idx += NT) {
        int dr = idx / H, x = idx - dr * H;
        const float* dnr = sdn + dr * HT2;
        int lc = (x >> 1) + 1;
        sup[idx] = (x & 1) ? 4.f * (dnr[lc] + dnr[lc + 1])
                           : dnr[lc - 1] + 6.f * dnr[lc] + dnr[lc + 1];
    }
    __syncthreads();
    float lsum = 0.f;
    for (int idx = tid; idx < H * H; idx += NT) {
        int y = idx / H, x = idx - y * H;
        int lr = (y >> 1) + 1;
        float u = (y & 1) ? 4.f * (sup[lr*H + x] + sup[(lr+1)*H + x])
                          : sup[(lr-1)*H + x] + 6.f*sup[lr*H + x] + sup[(lr+1)*H + x];
        lsum += fabsf(sa[y * H + x] - u * (1.f/64.f));
    }
    block_reduce_atomic(lsum, 4, sred);
}

__global__ void finalize_kernel(float* out) {
    if (threadIdx.x == 0 && blockIdx.x == 0) {
        double tot = 0.0;
        const int hs[NLVL] = {512, 256, 128, 64, 32};
#pragma unroll
        for (int l = 0; l < NLVL; l++) {
            double numel = (double)BC * hs[l] * hs[l];
            tot += g_sums[l] / numel;
        }
        out[0] = (float)tot;
    }
}

extern "C" void kernel_launch(void* const* d_in, const int* in_sizes, int n_in,
                              void* d_out, int out_size) {
    const float* input  = (const float*)d_in[0];
    const float* target = (const float*)d_in[1];
    float* out = (float*)d_out;

    const int OFF0 = 0;
    const int OFF1 = BC * 256*256;
    const int OFF2 = OFF1 + BC * 128*128;
    const int OFF3 = OFF2 + BC * 64*64;

    zero_sums_kernel<<<1, 32>>>();

    // L0: H=512, T64, 8x8 tiles
    lvl_kernel<64, 512, true ><<<dim3(64, BC), 512>>>(input,  target,  0,    OFF0, 512, 0, 8);
    // L1: H=256, T64, 4x4
    lvl_kernel<64, 512, false><<<dim3(16, BC), 512>>>(nullptr, nullptr, OFF0, OFF1, 256, 1, 4);
    // L2: H=128, T32, 4x4
    lvl_kernel<32, 256, false><<<dim3(16, BC), 256>>>(nullptr, nullptr, OFF1, OFF2, 128, 2, 4);
    // L3: H=64, T32, 2x2
    lvl_kernel<32, 256, false><<<dim3(4,  BC), 256>>>(nullptr, nullptr, OFF2, OFF3,  64, 3, 2);
    // L4: H=32, whole plane per block
    lvl4_kernel<<<BC, 256>>>(OFF3);

    finalize_kernel<<<1, 32>>>(out);
}

// round 8
// speedup vs baseline: 1.0024x; 1.0024x over previous
#include <cuda_runtime.h>
#include <cuda_bf16.h>

// Laplacian-pyramid L1 loss, 5 levels, (32,3,512,512) fp32.
// pyr(in)-pyr(tg) == pyr(in-tg); reflect padding is scale-consistent so the
// upsample needs only a 1-halo down tile. Even/odd deinterleave keeps smem
// unit-stride. R8: 4 launches total (zero+finalize folded into tail kernel).

#define BC 96
#define NLVL 5

__device__ __align__(16) float g_scratch[BC * (256*256 + 128*128 + 64*64)];
__device__ double g_sums[NLVL];          // static zero-init; reset by tail kernel
__device__ unsigned int g_ticket = 0;    // last-block election in tail kernel

__device__ __forceinline__ int refl(int t, int n) {
    if (t < 0)  return -t;
    if (t >= n) return 2*n - 2 - t;
    return t;
}
__device__ __forceinline__ float wt(int i) {
    return (i == 0 || i == 4) ? 1.0f : ((i == 2) ? 6.0f : 4.0f);
}
__device__ __forceinline__ float4 ld4(const float* p) {
    return *reinterpret_cast<const float4*>(p);
}
__device__ __forceinline__ void st4(float* p, float4 v) {
    *reinterpret_cast<float4*>(p) = v;
}
__device__ __forceinline__ float2 ld2(const float* p) {
    return *reinterpret_cast<const float2*>(p);
}
__device__ __forceinline__ void st2(float* p, float2 v) {
    *reinterpret_cast<float2*>(p) = v;
}

__device__ __forceinline__ void block_reduce_atomic(float v, int lvl, float* sred) {
    const int tid = threadIdx.x;
#pragma unroll
    for (int o = 16; o; o >>= 1) v += __shfl_down_sync(0xffffffffu, v, o);
    if ((tid & 31) == 0) sred[tid >> 5] = v;
    __syncthreads();
    if (tid < 16) {
        float x = (tid < (int)(blockDim.x >> 5)) ? sred[tid] : 0.f;
#pragma unroll
        for (int o = 8; o; o >>= 1) x += __shfl_down_sync(0xffffu, x, o);
        if (tid == 0) atomicAdd(&g_sums[lvl], (double)x);
    }
    __syncthreads();
}

// ---------------- tiled kernel: levels 0..2 (TILE=64, 512 thr) ----------------
template <bool DIFF>
__global__ __launch_bounds__(512)
void lvl_kernel(const float* __restrict__ a, const float* __restrict__ b,
                int srcOff, int dstOff, int H, int lvl, int tilesRow)
{
    constexpr int TILE = 64;
    constexpr int DT = 72;            // full-res rows (tile + 4-halo)
    constexpr int DC = 18;            // float4 chunks per full-res row
    constexpr int PE = 40;            // pitch of sdE/sdO
    constexpr int HT = 34;            // down rows (+1-halo)
    constexpr int HP = 36;            // st/sdn pitch
    constexpr int HI = 32;            // down interior
    constexpr int NT = 512;

    __shared__ float sdE[DT * PE];    // even full-res columns
    __shared__ float sdO[DT * PE];    // odd  full-res columns
    __shared__ float st [DT * HP];    // hgauss temp; later supE[34*32]+supO[34*32]
    __shared__ float sdn[HT * HP];
    __shared__ float sred[16];

    const int W = H, h = H >> 1;
    const int tid = threadIdx.x;
    const int ty = blockIdx.x / tilesRow, tx = blockIdx.x - ty * tilesRow;
    const int bc = blockIdx.y;
    const int y0 = ty * TILE, x0 = tx * TILE;
    const int r0 = y0 >> 1,  c0 = x0 >> 1;

    const float* sa = DIFF ? a + (size_t)bc * H * W
                           : g_scratch + srcOff + (size_t)bc * H * W;
    const float* sb = DIFF ? b + (size_t)bc * H * W : nullptr;

    // ---- load diff tile, deinterleave even/odd columns ----
    {
        int row = tid / DC, col = tid - row * DC;
        constexpr int dR = NT / DC, dC = NT % DC;   // 28, 8
        for (int it = tid; it < DT * DC; it += NT) {
            int gy  = y0 - 4 + row;
            int gx0 = x0 - 4 + 4 * col;
            float4 v;
            if (gy >= 0 && gy < H && gx0 >= 0 && gx0 + 3 < W) {
                size_t g = (size_t)gy * W + gx0;
                if (DIFF) {
                    float4 x1 = __ldcs(reinterpret_cast<const float4*>(sa + g));
                    float4 x2 = __ldcs(reinterpret_cast<const float4*>(sb + g));
                    v = make_float4(x1.x - x2.x, x1.y - x2.y, x1.z - x2.z, x1.w - x2.w);
                } else {
                    v = ld4(sa + g);
                }
            } else {
                int yy = refl(gy, H);
                float t[4];
#pragma unroll
                for (int k = 0; k < 4; k++) {
                    int xx = refl(gx0 + k, W);
                    size_t g = (size_t)yy * W + xx;
                    t[k] = sa[g];
                    if (DIFF) t[k] -= sb[g];
                }
                v = make_float4(t[0], t[1], t[2], t[3]);
            }
            st2(sdE + row * PE + 2 * col, make_float2(v.x, v.z));
            st2(sdO + row * PE + 2 * col, make_float2(v.y, v.w));
            row += dR; col += dC;
            if (col >= DC) { col -= DC; row++; }
        }
    }
    __syncthreads();

    // ---- horizontal gauss (stride-2 folded into parity arrays) ----
    {
        int r = tid / 9, k = tid - (tid / 9) * 9;
        constexpr int dR = NT / 9, dC = NT % 9;     // 56, 8
        for (int it = tid; it < DT * 9; it += NT) {
            const float* Er = sdE + r * PE + 4 * k;
            const float* Or = sdO + r * PE + 4 * k;
            float4 Ea = ld4(Er), Eb = ld4(Er + 4);
            float4 Oa = ld4(Or), Ob = ld4(Or + 4);
            float4 o;
            o.x = Ea.x + 6.f*Ea.y + Ea.z + 4.f*(Oa.x + Oa.y);
            o.y = Ea.y + 6.f*Ea.z + Ea.w + 4.f*(Oa.y + Oa.z);
            o.z = Ea.z + 6.f*Ea.w + Eb.x + 4.f*(Oa.z + Oa.w);
            o.w = Ea.w + 6.f*Eb.x + Eb.y + 4.f*(Oa.w + Ob.x);
            st4(st + r * HP + 4 * k, o);
            r += dR; k += dC;
            if (k >= 9) { k -= 9; r++; }
        }
    }
    __syncthreads();

    // ---- vertical gauss, stride 2 ----
    for (int it = tid; it < HT * 9; it += NT) {
        int r = it / 9, ck = it - r * 9;
        const float* base = st + (2 * r) * HP + 4 * ck;
        float4 r0v = ld4(base),        r1v = ld4(base + HP),
               r2v = ld4(base + 2*HP), r3v = ld4(base + 3*HP),
               r4v = ld4(base + 4*HP);
        float4 o;
        o.x = (r0v.x + 4.f*r1v.x + 6.f*r2v.x + 4.f*r3v.x + r4v.x) * (1.f/256.f);
        o.y = (r0v.y + 4.f*r1v.y + 6.f*r2v.y + 4.f*r3v.y + r4v.y) * (1.f/256.f);
        o.z = (r0v.z + 4.f*r1v.z + 6.f*r2v.z + 4.f*r3v.z + r4v.z) * (1.f/256.f);
        o.w = (r0v.w + 4.f*r1v.w + 6.f*r2v.w + 4.f*r3v.w + r4v.w) * (1.f/256.f);
        st4(sdn + r * HP + 4 * ck, o);
    }
    __syncthreads();

    // ---- write interior down tile (next level source) ----
    {
        float* gdn = g_scratch + dstOff + (size_t)bc * h * h;
        for (int it = tid; it < HI * 8; it += NT) {
            int r = it >> 3, ck = it & 7;
            const float* s = sdn + (r + 1) * HP + 4 * ck + 1;
            st4(gdn + (size_t)(r0 + r) * h + c0 + 4 * ck,
                make_float4(s[0], s[1], s[2], s[3]));
        }
    }

    // ---- horizontal upsample into parity-split sup ----
    float* supE = st;                 // st dead after vgauss
    float* supO = st + HT * 32;
    for (int it = tid; it < HT * 8; it += NT) {
        int dr = it >> 3, k = it & 7;
        const float* dnr = sdn + dr * HP + 4 * k;
        float4 A = ld4(dnr), B = ld4(dnr + 4);
        float4 e, o;
        e.x = A.x + 6.f*A.y + A.z;  o.x = 4.f*(A.y + A.z);
        e.y = A.y + 6.f*A.z + A.w;  o.y = 4.f*(A.z + A.w);
        e.z = A.z + 6.f*A.w + B.x;  o.z = 4.f*(A.w + B.x);
        e.w = A.w + 6.f*B.x + B.y;  o.w = 4.f*(B.x + B.y);
        st4(supE + dr * 32 + 4 * k, e);
        st4(supO + dr * 32 + 4 * k, o);
    }
    __syncthreads();

    // ---- vertical upsample + |d - up| (8 px/thread) ----
    float lsum = 0.0f;
    for (int it = tid; it < TILE * 8; it += NT) {
        int y = it >> 3, k = it & 7;
        int lr = (y >> 1) + 1;
        const float* pE = supE + lr * 32 + 4 * k;
        const float* pO = supO + lr * 32 + 4 * k;
        float4 uE, uO;
        if (y & 1) {
            float4 bE = ld4(pE), cE = ld4(pE + 32);
            float4 bO = ld4(pO), cO = ld4(pO + 32);
            uE.x = 4.f*(bE.x+cE.x); uE.y = 4.f*(bE.y+cE.y);
            uE.z = 4.f*(bE.z+cE.z); uE.w = 4.f*(bE.w+cE.w);
            uO.x = 4.f*(bO.x+cO.x); uO.y = 4.f*(bO.y+cO.y);
            uO.z = 4.f*(bO.z+cO.z); uO.w = 4.f*(bO.w+cO.w);
        } else {
            float4 aE = ld4(pE - 32), bE = ld4(pE), cE = ld4(pE + 32);
            float4 aO = ld4(pO - 32), bO = ld4(pO), cO = ld4(pO + 32);
            uE.x = aE.x + 6.f*bE.x + cE.x; uE.y = aE.y + 6.f*bE.y + cE.y;
            uE.z = aE.z + 6.f*bE.z + cE.z; uE.w = aE.w + 6.f*bE.w + cE.w;
            uO.x = aO.x + 6.f*bO.x + cO.x; uO.y = aO.y + 6.f*bO.y + cO.y;
            uO.z = aO.z + 6.f*bO.z + cO.z; uO.w = aO.w + 6.f*bO.w + cO.w;
        }
        int off = (y + 4) * PE + 4 * k + 2;
        float2 dEa = ld2(sdE + off), dEb = ld2(sdE + off + 2);
        float2 dOa = ld2(sdO + off), dOb = ld2(sdO + off + 2);
        lsum += fabsf(dEa.x - uE.x*(1.f/64.f)) + fabsf(dEa.y - uE.y*(1.f/64.f))
              + fabsf(dEb.x - uE.z*(1.f/64.f)) + fabsf(dEb.y - uE.w*(1.f/64.f))
              + fabsf(dOa.x - uO.x*(1.f/64.f)) + fabsf(dOa.y - uO.y*(1.f/64.f))
              + fabsf(dOb.x - uO.z*(1.f/64.f)) + fabsf(dOb.y - uO.w*(1.f/64.f));
    }
    block_reduce_atomic(lsum, lvl, sred);
}

// ---------------- in-smem level step (whole plane resident) ----------------
__device__ __forceinline__ void level_smem(const float* src, int sStride, int H,
                                           float* st, float* sdn,
                                           float& lsum, int tid, int NT)
{
    const int h = H >> 1, HT2 = h + 2;
    for (int idx = tid; idx < H * HT2; idx += NT) {
        int y = idx / HT2, dc = idx - y * HT2;
        const float* row = src + y * sStride;
        float acc = 0.f;
#pragma unroll
        for (int j = 0; j < 5; j++) acc += wt(j) * row[refl(2*dc - 4 + j, H)];
        st[idx] = acc;
    }
    __syncthreads();
    for (int idx = tid; idx < HT2 * HT2; idx += NT) {
        int dr = idx / HT2, dc = idx - dr * HT2;
        float acc = 0.f;
#pragma unroll
        for (int i = 0; i < 5; i++) acc += wt(i) * st[refl(2*dr - 4 + i, H) * HT2 + dc];
        sdn[idx] = acc * (1.f/256.f);
    }
    __syncthreads();
    float* sup = st;
    for (int idx = tid; idx < HT2 * H; idx += NT) {
        int dr = idx / H, x = idx - dr * H;
        const float* dnr = sdn + dr * HT2;
        int lc = (x >> 1) + 1;
        sup[idx] = (x & 1) ? 4.f * (dnr[lc] + dnr[lc + 1])
                           : dnr[lc - 1] + 6.f * dnr[lc] + dnr[lc + 1];
    }
    __syncthreads();
    for (int idx = tid; idx < H * H; idx += NT) {
        int y = idx / H, x = idx - y * H;
        int lr = (y >> 1) + 1;
        float u = (y & 1) ? 4.f * (sup[lr*H + x] + sup[(lr+1)*H + x])
                          : sup[(lr-1)*H + x] + 6.f*sup[lr*H + x] + sup[(lr+1)*H + x];
        lsum += fabsf(src[y * sStride + x] - u * (1.f/64.f));
    }
    __syncthreads();
}

// -------- fused levels 3+4 + final reduction: one block per bc-plane --------
__global__ __launch_bounds__(512)
void tail_kernel(int srcOff, float* __restrict__ out)
{
    __shared__ float sa  [64 * 64];
    __shared__ float st3 [64 * 34];
    __shared__ float sdn3[34 * 34];
    __shared__ float st4m[32 * 18];
    __shared__ float sdn4[18 * 18];
    __shared__ float sred[16];

    const int tid = threadIdx.x, NT = blockDim.x;
    const int bc = blockIdx.x;

    const float* g = g_scratch + srcOff + (size_t)bc * 64 * 64;
    for (int idx = tid; idx < 64 * 64 / 4; idx += NT)
        st4(sa + 4*idx, ld4(g + 4*idx));
    __syncthreads();

    float l3 = 0.f, l4 = 0.f;
    level_smem(sa, 64, 64, st3, sdn3, l3, tid, NT);
    block_reduce_atomic(l3, 3, sred);
    level_smem(sdn3 + 34 + 1, 34, 32, st4m, sdn4, l4, tid, NT);
    block_reduce_atomic(l4, 4, sred);

    // ---- last block finalizes: write loss, reset state for next replay ----
    if (tid == 0) {
        __threadfence();
        unsigned int t = atomicAdd(&g_ticket, 1u);
        if (t == gridDim.x - 1) {
            const double inv[NLVL] = {
                1.0 / ((double)BC * 512 * 512),
                1.0 / ((double)BC * 256 * 256),
                1.0 / ((double)BC * 128 * 128),
                1.0 / ((double)BC *  64 *  64),
                1.0 / ((double)BC *  32 *  32)
            };
            double tot = 0.0;
#pragma unroll
            for (int l = 0; l < NLVL; l++) tot += g_sums[l] * inv[l];
            out[0] = (float)tot;
#pragma unroll
            for (int l = 0; l < NLVL; l++) g_sums[l] = 0.0;   // next call starts clean
            g_ticket = 0;
            __threadfence();
        }
    }
}

extern "C" void kernel_launch(void* const* d_in, const int* in_sizes, int n_in,
                              void* d_out, int out_size) {
    const float* input  = (const float*)d_in[0];
    const float* target = (const float*)d_in[1];
    float* out = (float*)d_out;

    const int OFF0 = 0;
    const int OFF1 = BC * 256*256;
    const int OFF2 = OFF1 + BC * 128*128;

    lvl_kernel<true ><<<dim3(64, BC), 512>>>(input,  target,  0,    OFF0, 512, 0, 8);
    lvl_kernel<false><<<dim3(16, BC), 512>>>(nullptr, nullptr, OFF0, OFF1, 256, 1, 4);
    lvl_kernel<false><<<dim3(4,  BC), 512>>>(nullptr, nullptr, OFF1, OFF2, 128, 2, 2);
    tail_kernel<<<BC, 512>>>(OFF2, out);
}

// round 9
// speedup vs baseline: 1.0876x; 1.0849x over previous
#include <cuda_runtime.h>
#include <cuda_bf16.h>

// Laplacian-pyramid L1 loss, 5 levels, (32,3,512,512) fp32.
// pyr(in)-pyr(tg) == pyr(in-tg); reflect padding is scale-consistent so the
// upsample needs only a 1-halo down tile. Even/odd deinterleave keeps smem
// unit-stride. R9: interior fast-path loads + paired divergence-free vup.

#define BC 96
#define NLVL 5

__device__ __align__(16) float g_scratch[BC * (256*256 + 128*128 + 64*64)];
__device__ double g_sums[NLVL];          // static zero-init; reset by tail kernel
__device__ unsigned int g_ticket = 0;

__device__ __forceinline__ int refl(int t, int n) {
    if (t < 0)  return -t;
    if (t >= n) return 2*n - 2 - t;
    return t;
}
__device__ __forceinline__ float wt(int i) {
    return (i == 0 || i == 4) ? 1.0f : ((i == 2) ? 6.0f : 4.0f);
}
__device__ __forceinline__ float4 ld4(const float* p) {
    return *reinterpret_cast<const float4*>(p);
}
__device__ __forceinline__ void st4(float* p, float4 v) {
    *reinterpret_cast<float4*>(p) = v;
}
__device__ __forceinline__ float2 ld2(const float* p) {
    return *reinterpret_cast<const float2*>(p);
}
__device__ __forceinline__ void st2(float* p, float2 v) {
    *reinterpret_cast<float2*>(p) = v;
}

__device__ __forceinline__ void block_reduce_atomic(float v, int lvl, float* sred) {
    const int tid = threadIdx.x;
#pragma unroll
    for (int o = 16; o; o >>= 1) v += __shfl_down_sync(0xffffffffu, v, o);
    if ((tid & 31) == 0) sred[tid >> 5] = v;
    __syncthreads();
    if (tid < 16) {
        float x = (tid < (int)(blockDim.x >> 5)) ? sred[tid] : 0.f;
#pragma unroll
        for (int o = 8; o; o >>= 1) x += __shfl_down_sync(0xffffu, x, o);
        if (tid == 0) atomicAdd(&g_sums[lvl], (double)x);
    }
    __syncthreads();
}

// ---------------- tiled kernel: levels 0..2 (TILE=64, 512 thr) ----------------
template <bool DIFF>
__global__ __launch_bounds__(512)
void lvl_kernel(const float* __restrict__ a, const float* __restrict__ b,
                int srcOff, int dstOff, int H, int lvl, int tilesRow)
{
    constexpr int TILE = 64;
    constexpr int DT = 72;            // full-res rows (tile + 4-halo)
    constexpr int DC = 18;            // float4 chunks per full-res row
    constexpr int PE = 40;            // pitch of sdE/sdO
    constexpr int HT = 34;            // down rows (+1-halo)
    constexpr int HP = 36;            // st/sdn pitch
    constexpr int HI = 32;            // down interior
    constexpr int NT = 512;

    __shared__ float sdE[DT * PE];
    __shared__ float sdO[DT * PE];
    __shared__ float st [DT * HP];    // hgauss temp; later supE[34*32]+supO[34*32]
    __shared__ float sdn[HT * HP];
    __shared__ float sred[16];

    const int W = H, h = H >> 1;
    const int tid = threadIdx.x;
    const int ty = blockIdx.x / tilesRow, tx = blockIdx.x - ty * tilesRow;
    const int bc = blockIdx.y;
    const int y0 = ty * TILE, x0 = tx * TILE;
    const int r0 = y0 >> 1,  c0 = x0 >> 1;

    const float* sa = DIFF ? a + (size_t)bc * H * W
                           : g_scratch + srcOff + (size_t)bc * H * W;
    const float* sb = DIFF ? b + (size_t)bc * H * W : nullptr;

    // ---- load diff tile, deinterleave even/odd columns ----
    const bool interior = (y0 >= 4) & (y0 + TILE + 4 <= H) &
                          (x0 >= 4) & (x0 + TILE + 4 <= W);
    if (interior) {
        const float* pa = sa + (size_t)(y0 - 4) * W + (x0 - 4);
        const float* pb = DIFF ? sb + (size_t)(y0 - 4) * W + (x0 - 4) : nullptr;
        for (int it = tid; it < DT * DC; it += NT) {
            int row = it / DC, col = it - row * DC;
            size_t g = (size_t)row * W + 4 * col;
            float4 v;
            if (DIFF) {
                float4 x1 = __ldcs(reinterpret_cast<const float4*>(pa + g));
                float4 x2 = __ldcs(reinterpret_cast<const float4*>(pb + g));
                v = make_float4(x1.x - x2.x, x1.y - x2.y, x1.z - x2.z, x1.w - x2.w);
            } else {
                v = ld4(pa + g);
            }
            st2(sdE + row * PE + 2 * col, make_float2(v.x, v.z));
            st2(sdO + row * PE + 2 * col, make_float2(v.y, v.w));
        }
    } else {
        for (int it = tid; it < DT * DC; it += NT) {
            int row = it / DC, col = it - row * DC;
            int gy  = y0 - 4 + row;
            int gx0 = x0 - 4 + 4 * col;
            float4 v;
            if (gy >= 0 && gy < H && gx0 >= 0 && gx0 + 3 < W) {
                size_t g = (size_t)gy * W + gx0;
                v = ld4(sa + g);
                if (DIFF) {
                    float4 w = ld4(sb + g);
                    v.x -= w.x; v.y -= w.y; v.z -= w.z; v.w -= w.w;
                }
            } else {
                int yy = refl(gy, H);
                float t[4];
#pragma unroll
                for (int k = 0; k < 4; k++) {
                    int xx = refl(gx0 + k, W);
                    size_t g = (size_t)yy * W + xx;
                    t[k] = sa[g];
                    if (DIFF) t[k] -= sb[g];
                }
                v = make_float4(t[0], t[1], t[2], t[3]);
            }
            st2(sdE + row * PE + 2 * col, make_float2(v.x, v.z));
            st2(sdO + row * PE + 2 * col, make_float2(v.y, v.w));
        }
    }
    __syncthreads();

    // ---- horizontal gauss (stride-2 folded into parity arrays) ----
    for (int it = tid; it < DT * 9; it += NT) {
        int r = it / 9, k = it - r * 9;
        const float* Er = sdE + r * PE + 4 * k;
        const float* Or = sdO + r * PE + 4 * k;
        float4 Ea = ld4(Er), Eb = ld4(Er + 4);
        float4 Oa = ld4(Or), Ob = ld4(Or + 4);
        float4 o;
        o.x = Ea.x + 6.f*Ea.y + Ea.z + 4.f*(Oa.x + Oa.y);
        o.y = Ea.y + 6.f*Ea.z + Ea.w + 4.f*(Oa.y + Oa.z);
        o.z = Ea.z + 6.f*Ea.w + Eb.x + 4.f*(Oa.z + Oa.w);
        o.w = Ea.w + 6.f*Eb.x + Eb.y + 4.f*(Oa.w + Ob.x);
        st4(st + r * HP + 4 * k, o);
    }
    __syncthreads();

    // ---- vertical gauss, stride 2 ----
    for (int it = tid; it < HT * 9; it += NT) {
        int r = it / 9, ck = it - r * 9;
        const float* base = st + (2 * r) * HP + 4 * ck;
        float4 r0v = ld4(base),        r1v = ld4(base + HP),
               r2v = ld4(base + 2*HP), r3v = ld4(base + 3*HP),
               r4v = ld4(base + 4*HP);
        float4 o;
        o.x = (r0v.x + 4.f*r1v.x + 6.f*r2v.x + 4.f*r3v.x + r4v.x) * (1.f/256.f);
        o.y = (r0v.y + 4.f*r1v.y + 6.f*r2v.y + 4.f*r3v.y + r4v.y) * (1.f/256.f);
        o.z = (r0v.z + 4.f*r1v.z + 6.f*r2v.z + 4.f*r3v.z + r4v.z) * (1.f/256.f);
        o.w = (r0v.w + 4.f*r1v.w + 6.f*r2v.w + 4.f*r3v.w + r4v.w) * (1.f/256.f);
        st4(sdn + r * HP + 4 * ck, o);
    }
    __syncthreads();

    // ---- write interior down tile (next level source) ----
    {
        float* gdn = g_scratch + dstOff + (size_t)bc * h * h;
        for (int it = tid; it < HI * 8; it += NT) {
            int r = it >> 3, ck = it & 7;
            const float* s = sdn + (r + 1) * HP + 4 * ck + 1;
            st4(gdn + (size_t)(r0 + r) * h + c0 + 4 * ck,
                make_float4(s[0], s[1], s[2], s[3]));
        }
    }

    // ---- horizontal upsample into parity-split sup ----
    float* supE = st;                 // st dead after vgauss
    float* supO = st + HT * 32;
    for (int it = tid; it < HT * 8; it += NT) {
        int dr = it >> 3, k = it & 7;
        const float* dnr = sdn + dr * HP + 4 * k;
        float4 A = ld4(dnr), B = ld4(dnr + 4);
        float4 e, o;
        e.x = A.x + 6.f*A.y + A.z;  o.x = 4.f*(A.y + A.z);
        e.y = A.y + 6.f*A.z + A.w;  o.y = 4.f*(A.z + A.w);
        e.z = A.z + 6.f*A.w + B.x;  o.z = 4.f*(A.w + B.x);
        e.w = A.w + 6.f*B.x + B.y;  o.w = 4.f*(B.x + B.y);
        st4(supE + dr * 32 + 4 * k, e);
        st4(supO + dr * 32 + 4 * k, o);
    }
    __syncthreads();

    // ---- paired vertical upsample + |d - up|: y (even) and y+1 share taps ----
    // 512 threads, exactly one (ypair, k2) each: 16 px/thread, no divergence.
    float lsum = 0.0f;
    {
        int yp = tid >> 4;            // 0..31
        int k2 = tid & 15;            // float2 column chunk
        int lr = yp + 1;
        const float* pE = supE + lr * 32 + 2 * k2;
        const float* pO = supO + lr * 32 + 2 * k2;
        float2 aE = ld2(pE - 32), bE = ld2(pE), cE = ld2(pE + 32);
        float2 aO = ld2(pO - 32), bO = ld2(pO), cO = ld2(pO + 32);

        int y = 2 * yp;
        int offE = (y + 4) * PE + 2 * k2 + 2;
        float2 dE0 = ld2(sdE + offE),      dO0 = ld2(sdO + offE);
        float2 dE1 = ld2(sdE + offE + PE), dO1 = ld2(sdO + offE + PE);

        // even row: (1,6,1) taps
        lsum += fabsf(dE0.x - (aE.x + 6.f*bE.x + cE.x) * (1.f/64.f))
              + fabsf(dE0.y - (aE.y + 6.f*bE.y + cE.y) * (1.f/64.f))
              + fabsf(dO0.x - (aO.x + 6.f*bO.x + cO.x) * (1.f/64.f))
              + fabsf(dO0.y - (aO.y + 6.f*bO.y + cO.y) * (1.f/64.f));
        // odd row: 4*(b+c) taps
        lsum += fabsf(dE1.x - (bE.x + cE.x) * (4.f/64.f))
              + fabsf(dE1.y - (bE.y + cE.y) * (4.f/64.f))
              + fabsf(dO1.x - (bO.x + cO.x) * (4.f/64.f))
              + fabsf(dO1.y - (bO.y + cO.y) * (4.f/64.f));
    }
    block_reduce_atomic(lsum, lvl, sred);
}

// ---------------- in-smem level step (whole plane resident) ----------------
__device__ __forceinline__ void level_smem(const float* src, int sStride, int H,
                                           float* st, float* sdn,
                                           float& lsum, int tid, int NT)
{
    const int h = H >> 1, HT2 = h + 2;
    for (int idx = tid; idx < H * HT2; idx += NT) {
        int y = idx / HT2, dc = idx - y * HT2;
        const float* row = src + y * sStride;
        float acc = 0.f;
#pragma unroll
        for (int j = 0; j < 5; j++) acc += wt(j) * row[refl(2*dc - 4 + j, H)];
        st[idx] = acc;
    }
    __syncthreads();
    for (int idx = tid; idx < HT2 * HT2; idx += NT) {
        int dr = idx / HT2, dc = idx - dr * HT2;
        float acc = 0.f;
#pragma unroll
        for (int i = 0; i < 5; i++) acc += wt(i) * st[refl(2*dr - 4 + i, H) * HT2 + dc];
        sdn[idx] = acc * (1.f/256.f);
    }
    __syncthreads();
    float* sup = st;
    for (int idx = tid; idx < HT2 * H; idx += NT) {
        int dr = idx / H, x = idx - dr * H;
        const float* dnr = sdn + dr * HT2;
        int lc = (x >> 1) + 1;
        sup[idx] = (x & 1) ? 4.f * (dnr[lc] + dnr[lc + 1])
                           : dnr[lc - 1] + 6.f * dnr[lc] + dnr[lc + 1];
    }
    __syncthreads();
    for (int idx = tid; idx < H * H; idx += NT) {
        int y = idx / H, x = idx - y * H;
        int lr = (y >> 1) + 1;
        float u = (y & 1) ? 4.f * (sup[lr*H + x] + sup[(lr+1)*H + x])
                          : sup[(lr-1)*H + x] + 6.f*sup[lr*H + x] + sup[(lr+1)*H + x];
        lsum += fabsf(src[y * sStride + x] - u * (1.f/64.f));
    }
    __syncthreads();
}

// -------- fused levels 3+4 + final reduction: one block per bc-plane --------
__global__ __launch_bounds__(512)
void tail_kernel(int srcOff, float* __restrict__ out)
{
    __shared__ float sa  [64 * 64];
    __shared__ float st3 [64 * 34];
    __shared__ float sdn3[34 * 34];
    __shared__ float st4m[32 * 18];
    __shared__ float sdn4[18 * 18];
    __shared__ float sred[16];

    const int tid = threadIdx.x, NT = blockDim.x;
    const int bc = blockIdx.x;

    const float* g = g_scratch + srcOff + (size_t)bc * 64 * 64;
    for (int idx = tid; idx < 64 * 64 / 4; idx += NT)
        st4(sa + 4*idx, ld4(g + 4*idx));
    __syncthreads();

    float l3 = 0.f, l4 = 0.f;
    level_smem(sa, 64, 64, st3, sdn3, l3, tid, NT);
    block_reduce_atomic(l3, 3, sred);
    level_smem(sdn3 + 34 + 1, 34, 32, st4m, sdn4, l4, tid, NT);
    block_reduce_atomic(l4, 4, sred);

    if (tid == 0) {
        __threadfence();
        unsigned int t = atomicAdd(&g_ticket, 1u);
        if (t == gridDim.x - 1) {
            const double inv[NLVL] = {
                1.0 / ((double)BC * 512 * 512),
                1.0 / ((double)BC * 256 * 256),
                1.0 / ((double)BC * 128 * 128),
                1.0 / ((double)BC *  64 *  64),
                1.0 / ((double)BC *  32 *  32)
            };
            double tot = 0.0;
#pragma unroll
            for (int l = 0; l < NLVL; l++) tot += g_sums[l] * inv[l];
            out[0] = (float)tot;
#pragma unroll
            for (int l = 0; l < NLVL; l++) g_sums[l] = 0.0;
            g_ticket = 0;
            __threadfence();
        }
    }
}

extern "C" void kernel_launch(void* const* d_in, const int* in_sizes, int n_in,
                              void* d_out, int out_size) {
    const float* input  = (const float*)d_in[0];
    const float* target = (const float*)d_in[1];
    float* out = (float*)d_out;

    const int OFF0 = 0;
    const int OFF1 = BC * 256*256;
    const int OFF2 = OFF1 + BC * 128*128;

    lvl_kernel<true ><<<dim3(64, BC), 512>>>(input,  target,  0,    OFF0, 512, 0, 8);
    lvl_kernel<false><<<dim3(16, BC), 512>>>(nullptr, nullptr, OFF0, OFF1, 256, 1, 4);
    lvl_kernel<false><<<dim3(4,  BC), 512>>>(nullptr, nullptr, OFF1, OFF2, 128, 2, 2);
    tail_kernel<<<BC, 512>>>(OFF2, out);
}

// round 10
// speedup vs baseline: 1.1163x; 1.0265x over previous
#include <cuda_runtime.h>
#include <cuda_bf16.h>

// Laplacian-pyramid L1 loss, 5 levels, (32,3,512,512) fp32.
// pyr(in)-pyr(tg) == pyr(in-tg); reflect padding is scale-consistent so the
// upsample needs only a 1-halo down tile. Even/odd deinterleave keeps smem
// unit-stride. R10: direct 2D upsample from sdn (hup phase + barrier removed).

#define BC 96
#define NLVL 5

__device__ __align__(16) float g_scratch[BC * (256*256 + 128*128 + 64*64)];
__device__ double g_sums[NLVL];          // static zero-init; reset by tail kernel
__device__ unsigned int g_ticket = 0;

__device__ __forceinline__ int refl(int t, int n) {
    if (t < 0)  return -t;
    if (t >= n) return 2*n - 2 - t;
    return t;
}
__device__ __forceinline__ float wt(int i) {
    return (i == 0 || i == 4) ? 1.0f : ((i == 2) ? 6.0f : 4.0f);
}
__device__ __forceinline__ float4 ld4(const float* p) {
    return *reinterpret_cast<const float4*>(p);
}
__device__ __forceinline__ void st4(float* p, float4 v) {
    *reinterpret_cast<float4*>(p) = v;
}
__device__ __forceinline__ float2 ld2(const float* p) {
    return *reinterpret_cast<const float2*>(p);
}
__device__ __forceinline__ void st2(float* p, float2 v) {
    *reinterpret_cast<float2*>(p) = v;
}

__device__ __forceinline__ void block_reduce_atomic(float v, int lvl, float* sred) {
    const int tid = threadIdx.x;
#pragma unroll
    for (int o = 16; o; o >>= 1) v += __shfl_down_sync(0xffffffffu, v, o);
    if ((tid & 31) == 0) sred[tid >> 5] = v;
    __syncthreads();
    if (tid < 16) {
        float x = (tid < (int)(blockDim.x >> 5)) ? sred[tid] : 0.f;
#pragma unroll
        for (int o = 8; o; o >>= 1) x += __shfl_down_sync(0xffffu, x, o);
        if (tid == 0) atomicAdd(&g_sums[lvl], (double)x);
    }
    __syncthreads();
}

// ---------------- tiled kernel: levels 0..2 (TILE=64, 512 thr) ----------------
template <bool DIFF>
__global__ __launch_bounds__(512)
void lvl_kernel(const float* __restrict__ a, const float* __restrict__ b,
                int srcOff, int dstOff, int H, int lvl, int tilesRow)
{
    constexpr int TILE = 64;
    constexpr int DT = 72;            // full-res rows (tile + 4-halo)
    constexpr int DC = 18;            // float4 chunks per full-res row
    constexpr int PE = 40;            // pitch of sdE/sdO
    constexpr int HT = 34;            // down rows (+1-halo)
    constexpr int HP = 36;            // st/sdn pitch
    constexpr int HI = 32;            // down interior
    constexpr int NT = 512;

    __shared__ float sdE[DT * PE];
    __shared__ float sdO[DT * PE];
    __shared__ float st [DT * HP];    // hgauss temp
    __shared__ float sdn[HT * HP];
    __shared__ float sred[16];

    const int W = H, h = H >> 1;
    const int tid = threadIdx.x;
    const int ty = blockIdx.x / tilesRow, tx = blockIdx.x - ty * tilesRow;
    const int bc = blockIdx.y;
    const int y0 = ty * TILE, x0 = tx * TILE;
    const int r0 = y0 >> 1,  c0 = x0 >> 1;

    const float* sa = DIFF ? a + (size_t)bc * H * W
                           : g_scratch + srcOff + (size_t)bc * H * W;
    const float* sb = DIFF ? b + (size_t)bc * H * W : nullptr;

    // ---- load diff tile, deinterleave even/odd columns ----
    const bool interior = (y0 >= 4) & (y0 + TILE + 4 <= H) &
                          (x0 >= 4) & (x0 + TILE + 4 <= W);
    if (interior) {
        const float* pa = sa + (size_t)(y0 - 4) * W + (x0 - 4);
        const float* pb = DIFF ? sb + (size_t)(y0 - 4) * W + (x0 - 4) : nullptr;
        for (int it = tid; it < DT * DC; it += NT) {
            int row = it / DC, col = it - row * DC;
            size_t g = (size_t)row * W + 4 * col;
            float4 v;
            if (DIFF) {
                float4 x1 = __ldcs(reinterpret_cast<const float4*>(pa + g));
                float4 x2 = __ldcs(reinterpret_cast<const float4*>(pb + g));
                v = make_float4(x1.x - x2.x, x1.y - x2.y, x1.z - x2.z, x1.w - x2.w);
            } else {
                v = ld4(pa + g);
            }
            st2(sdE + row * PE + 2 * col, make_float2(v.x, v.z));
            st2(sdO + row * PE + 2 * col, make_float2(v.y, v.w));
        }
    } else {
        for (int it = tid; it < DT * DC; it += NT) {
            int row = it / DC, col = it - row * DC;
            int gy  = y0 - 4 + row;
            int gx0 = x0 - 4 + 4 * col;
            float4 v;
            if (gy >= 0 && gy < H && gx0 >= 0 && gx0 + 3 < W) {
                size_t g = (size_t)gy * W + gx0;
                v = ld4(sa + g);
                if (DIFF) {
                    float4 w = ld4(sb + g);
                    v.x -= w.x; v.y -= w.y; v.z -= w.z; v.w -= w.w;
                }
            } else {
                int yy = refl(gy, H);
                float t[4];
#pragma unroll
                for (int k = 0; k < 4; k++) {
                    int xx = refl(gx0 + k, W);
                    size_t g = (size_t)yy * W + xx;
                    t[k] = sa[g];
                    if (DIFF) t[k] -= sb[g];
                }
                v = make_float4(t[0], t[1], t[2], t[3]);
            }
            st2(sdE + row * PE + 2 * col, make_float2(v.x, v.z));
            st2(sdO + row * PE + 2 * col, make_float2(v.y, v.w));
        }
    }
    __syncthreads();

    // ---- horizontal gauss (stride-2 folded into parity arrays) ----
    for (int it = tid; it < DT * 9; it += NT) {
        int r = it / 9, k = it - r * 9;
        const float* Er = sdE + r * PE + 4 * k;
        const float* Or = sdO + r * PE + 4 * k;
        float4 Ea = ld4(Er), Eb = ld4(Er + 4);
        float4 Oa = ld4(Or), Ob = ld4(Or + 4);
        float4 o;
        o.x = Ea.x + 6.f*Ea.y + Ea.z + 4.f*(Oa.x + Oa.y);
        o.y = Ea.y + 6.f*Ea.z + Ea.w + 4.f*(Oa.y + Oa.z);
        o.z = Ea.z + 6.f*Ea.w + Eb.x + 4.f*(Oa.z + Oa.w);
        o.w = Ea.w + 6.f*Eb.x + Eb.y + 4.f*(Oa.w + Ob.x);
        st4(st + r * HP + 4 * k, o);
    }
    __syncthreads();

    // ---- vertical gauss, stride 2 ----
    for (int it = tid; it < HT * 9; it += NT) {
        int r = it / 9, ck = it - r * 9;
        const float* base = st + (2 * r) * HP + 4 * ck;
        float4 r0v = ld4(base),        r1v = ld4(base + HP),
               r2v = ld4(base + 2*HP), r3v = ld4(base + 3*HP),
               r4v = ld4(base + 4*HP);
        float4 o;
        o.x = (r0v.x + 4.f*r1v.x + 6.f*r2v.x + 4.f*r3v.x + r4v.x) * (1.f/256.f);
        o.y = (r0v.y + 4.f*r1v.y + 6.f*r2v.y + 4.f*r3v.y + r4v.y) * (1.f/256.f);
        o.z = (r0v.z + 4.f*r1v.z + 6.f*r2v.z + 4.f*r3v.z + r4v.z) * (1.f/256.f);
        o.w = (r0v.w + 4.f*r1v.w + 6.f*r2v.w + 4.f*r3v.w + r4v.w) * (1.f/256.f);
        st4(sdn + r * HP + 4 * ck, o);
    }
    __syncthreads();

    // ---- write interior down tile (next level source) ----
    {
        float* gdn = g_scratch + dstOff + (size_t)bc * h * h;
        for (int it = tid; it < HI * 8; it += NT) {
            int r = it >> 3, ck = it & 7;
            const float* s = sdn + (r + 1) * HP + 4 * ck + 1;
            st4(gdn + (size_t)(r0 + r) * h + c0 + 4 * ck,
                make_float4(s[0], s[1], s[2], s[3]));
        }
    }

    // ---- direct 2D upsample from sdn + |d - up| ----
    // 512 threads, one (row-pair, x-quad) each: y=2r,2r+1; x=4j..4j+3.
    // Needs sdn rows r..r+2, local cols 2j..2j+3. No divergence, no hup phase.
    float lsum = 0.0f;
    {
        const int r = tid >> 4;       // 0..31
        const int j = tid & 15;       // 0..15
        const float* base = sdn + r * HP + 2 * j;
        float2 A0 = ld2(base),          B0 = ld2(base + 2);
        float2 A1 = ld2(base + HP),     B1 = ld2(base + HP + 2);
        float2 A2 = ld2(base + 2*HP),   B2 = ld2(base + 2*HP + 2);

        // per-row horizontal sums: cols l0=A.x l1=A.y l2=B.x l3=B.y
        float h0A = A0.x + 6.f*A0.y + B0.x, h0B = A0.y + 6.f*B0.x + B0.y;
        float h0C = 4.f*(A0.y + B0.x),      h0D = 4.f*(B0.x + B0.y);
        float h1A = A1.x + 6.f*A1.y + B1.x, h1B = A1.y + 6.f*B1.x + B1.y;
        float h1C = 4.f*(A1.y + B1.x),      h1D = 4.f*(B1.x + B1.y);
        float h2A = A2.x + 6.f*A2.y + B2.x, h2B = A2.y + 6.f*B2.x + B2.y;
        float h2C = 4.f*(A2.y + B2.x),      h2D = 4.f*(B2.x + B2.y);

        constexpr float i64 = 1.f / 64.f;
        // even row y=2r: vertical (1,6,1) over rows r..r+2
        float u00 = (h0A + 6.f*h1A + h2A) * i64;   // x=4j   (E)
        float u01 = (h0C + 6.f*h1C + h2C) * i64;   // x=4j+1 (O)
        float u02 = (h0B + 6.f*h1B + h2B) * i64;   // x=4j+2 (E)
        float u03 = (h0D + 6.f*h1D + h2D) * i64;   // x=4j+3 (O)
        // odd row y=2r+1: vertical 4*(r+1, r+2)
        float u10 = (h1A + h2A) * (4.f * i64);
        float u11 = (h1C + h2C) * (4.f * i64);
        float u12 = (h1B + h2B) * (4.f * i64);
        float u13 = (h1D + h2D) * (4.f * i64);

        const int offE = (2*r + 4) * PE + 2 * j + 2;
        float2 dE0 = ld2(sdE + offE),      dO0 = ld2(sdO + offE);
        float2 dE1 = ld2(sdE + offE + PE), dO1 = ld2(sdO + offE + PE);

        lsum += fabsf(dE0.x - u00) + fabsf(dO0.x - u01)
              + fabsf(dE0.y - u02) + fabsf(dO0.y - u03)
              + fabsf(dE1.x - u10) + fabsf(dO1.x - u11)
              + fabsf(dE1.y - u12) + fabsf(dO1.y - u13);
    }
    block_reduce_atomic(lsum, lvl, sred);
}

// ---------------- in-smem level step (whole plane resident) ----------------
__device__ __forceinline__ void level_smem(const float* src, int sStride, int H,
                                           float* st, float* sdn,
                                           float& lsum, int tid, int NT)
{
    const int h = H >> 1, HT2 = h + 2;
    for (int idx = tid; idx < H * HT2; idx += NT) {
        int y = idx / HT2, dc = idx - y * HT2;
        const float* row = src + y * sStride;
        float acc = 0.f;
#pragma unroll
        for (int j = 0; j < 5; j++) acc += wt(j) * row[refl(2*dc - 4 + j, H)];
        st[idx] = acc;
    }
    __syncthreads();
    for (int idx = tid; idx < HT2 * HT2; idx += NT) {
        int dr = idx / HT2, dc = idx - dr * HT2;
        float acc = 0.f;
#pragma unroll
        for (int i = 0; i < 5; i++) acc += wt(i) * st[refl(2*dr - 4 + i, H) * HT2 + dc];
        sdn[idx] = acc * (1.f/256.f);
    }
    __syncthreads();
    float* sup = st;
    for (int idx = tid; idx < HT2 * H; idx += NT) {
        int dr = idx / H, x = idx - dr * H;
        const float* dnr = sdn + dr * HT2;
        int lc = (x >> 1) + 1;
        sup[idx] = (x & 1) ? 4.f * (dnr[lc] + dnr[lc + 1])
                           : dnr[lc - 1] + 6.f * dnr[lc] + dnr[lc + 1];
    }
    __syncthreads();
    for (int idx = tid; idx < H * H; idx += NT) {
        int y = idx / H, x = idx - y * H;
        int lr = (y >> 1) + 1;
        float u = (y & 1) ? 4.f * (sup[lr*H + x] + sup[(lr+1)*H + x])
                          : sup[(lr-1)*H + x] + 6.f*sup[lr*H + x] + sup[(lr+1)*H + x];
        lsum += fabsf(src[y * sStride + x] - u * (1.f/64.f));
    }
    __syncthreads();
}

// -------- fused levels 3+4 + final reduction: one block per bc-plane --------
__global__ __launch_bounds__(512)
void tail_kernel(int srcOff, float* __restrict__ out)
{
    __shared__ float sa  [64 * 64];
    __shared__ float st3 [64 * 34];
    __shared__ float sdn3[34 * 34];
    __shared__ float st4m[32 * 18];
    __shared__ float sdn4[18 * 18];
    __shared__ float sred[16];

    const int tid = threadIdx.x, NT = blockDim.x;
    const int bc = blockIdx.x;

    const float* g = g_scratch + srcOff + (size_t)bc * 64 * 64;
    for (int idx = tid; idx < 64 * 64 / 4; idx += NT)
        st4(sa + 4*idx, ld4(g + 4*idx));
    __syncthreads();

    float l3 = 0.f, l4 = 0.f;
    level_smem(sa, 64, 64, st3, sdn3, l3, tid, NT);
    block_reduce_atomic(l3, 3, sred);
    level_smem(sdn3 + 34 + 1, 34, 32, st4m, sdn4, l4, tid, NT);
    block_reduce_atomic(l4, 4, sred);

    if (tid == 0) {
        __threadfence();
        unsigned int t = atomicAdd(&g_ticket, 1u);
        if (t == gridDim.x - 1) {
            const double inv[NLVL] = {
                1.0 / ((double)BC * 512 * 512),
                1.0 / ((double)BC * 256 * 256),
                1.0 / ((double)BC * 128 * 128),
                1.0 / ((double)BC *  64 *  64),
                1.0 / ((double)BC *  32 *  32)
            };
            double tot = 0.0;
#pragma unroll
            for (int l = 0; l < NLVL; l++) tot += g_sums[l] * inv[l];
            out[0] = (float)tot;
#pragma unroll
            for (int l = 0; l < NLVL; l++) g_sums[l] = 0.0;
            g_ticket = 0;
            __threadfence();
        }
    }
}

extern "C" void kernel_launch(void* const* d_in, const int* in_sizes, int n_in,
                              void* d_out, int out_size) {
    const float* input  = (const float*)d_in[0];
    const float* target = (const float*)d_in[1];
    float* out = (float*)d_out;

    const int OFF0 = 0;
    const int OFF1 = BC * 256*256;
    const int OFF2 = OFF1 + BC * 128*128;

    lvl_kernel<true ><<<dim3(64, BC), 512>>>(input,  target,  0,    OFF0, 512, 0, 8);
    lvl_kernel<false><<<dim3(16, BC), 512>>>(nullptr, nullptr, OFF0, OFF1, 256, 1, 4);
    lvl_kernel<false><<<dim3(4,  BC), 512>>>(nullptr, nullptr, OFF1, OFF2, 128, 2, 2);
    tail_kernel<<<BC, 512>>>(OFF2, out);
}

// round 11
// speedup vs baseline: 1.1330x; 1.0149x over previous
#include <cuda_runtime.h>
#include <cuda_bf16.h>

// Laplacian-pyramid L1 loss, 5 levels, (32,3,512,512) fp32.
// pyr(in)-pyr(tg) == pyr(in-tg); reflect padding is scale-consistent so the
// upsample needs only a 1-halo down tile. Even/odd deinterleave keeps smem
// unit-stride. R11: tail rewritten phase-minimal (direct 2D vup, merged
// phases, combined reduce, interior fast paths).

#define BC 96
#define NLVL 5

__device__ __align__(16) float g_scratch[BC * (256*256 + 128*128 + 64*64)];
__device__ double g_sums[NLVL];          // static zero-init; reset by tail kernel
__device__ unsigned int g_ticket = 0;

__device__ __forceinline__ int refl(int t, int n) {
    if (t < 0)  return -t;
    if (t >= n) return 2*n - 2 - t;
    return t;
}
__device__ __forceinline__ float wt(int i) {
    return (i == 0 || i == 4) ? 1.0f : ((i == 2) ? 6.0f : 4.0f);
}
__device__ __forceinline__ float4 ld4(const float* p) {
    return *reinterpret_cast<const float4*>(p);
}
__device__ __forceinline__ void st4(float* p, float4 v) {
    *reinterpret_cast<float4*>(p) = v;
}
__device__ __forceinline__ float2 ld2(const float* p) {
    return *reinterpret_cast<const float2*>(p);
}
__device__ __forceinline__ void st2(float* p, float2 v) {
    *reinterpret_cast<float2*>(p) = v;
}

__device__ __forceinline__ void block_reduce_atomic(float v, int lvl, float* sred) {
    const int tid = threadIdx.x;
#pragma unroll
    for (int o = 16; o; o >>= 1) v += __shfl_down_sync(0xffffffffu, v, o);
    if ((tid & 31) == 0) sred[tid >> 5] = v;
    __syncthreads();
    if (tid < 16) {
        float x = (tid < (int)(blockDim.x >> 5)) ? sred[tid] : 0.f;
#pragma unroll
        for (int o = 8; o; o >>= 1) x += __shfl_down_sync(0xffffu, x, o);
        if (tid == 0) atomicAdd(&g_sums[lvl], (double)x);
    }
    __syncthreads();
}

// ---------------- tiled kernel: levels 0..2 (TILE=64, 512 thr) ----------------
template <bool DIFF>
__global__ __launch_bounds__(512)
void lvl_kernel(const float* __restrict__ a, const float* __restrict__ b,
                int srcOff, int dstOff, int H, int lvl, int tilesRow)
{
    constexpr int TILE = 64;
    constexpr int DT = 72;            // full-res rows (tile + 4-halo)
    constexpr int DC = 18;            // float4 chunks per full-res row
    constexpr int PE = 40;            // pitch of sdE/sdO
    constexpr int HT = 34;            // down rows (+1-halo)
    constexpr int HP = 36;            // st/sdn pitch
    constexpr int HI = 32;            // down interior
    constexpr int NT = 512;

    __shared__ __align__(16) float sdE[DT * PE];
    __shared__ __align__(16) float sdO[DT * PE];
    __shared__ __align__(16) float st [DT * HP];
    __shared__ __align__(16) float sdn[HT * HP];
    __shared__ float sred[16];

    const int W = H, h = H >> 1;
    const int tid = threadIdx.x;
    const int ty = blockIdx.x / tilesRow, tx = blockIdx.x - ty * tilesRow;
    const int bc = blockIdx.y;
    const int y0 = ty * TILE, x0 = tx * TILE;
    const int r0 = y0 >> 1,  c0 = x0 >> 1;

    const float* sa = DIFF ? a + (size_t)bc * H * W
                           : g_scratch + srcOff + (size_t)bc * H * W;
    const float* sb = DIFF ? b + (size_t)bc * H * W : nullptr;

    // ---- load diff tile, deinterleave even/odd columns ----
    const bool interior = (y0 >= 4) & (y0 + TILE + 4 <= H) &
                          (x0 >= 4) & (x0 + TILE + 4 <= W);
    if (interior) {
        const float* pa = sa + (size_t)(y0 - 4) * W + (x0 - 4);
        const float* pb = DIFF ? sb + (size_t)(y0 - 4) * W + (x0 - 4) : nullptr;
        for (int it = tid; it < DT * DC; it += NT) {
            int row = it / DC, col = it - row * DC;
            size_t g = (size_t)row * W + 4 * col;
            float4 v;
            if (DIFF) {
                float4 x1 = __ldcs(reinterpret_cast<const float4*>(pa + g));
                float4 x2 = __ldcs(reinterpret_cast<const float4*>(pb + g));
                v = make_float4(x1.x - x2.x, x1.y - x2.y, x1.z - x2.z, x1.w - x2.w);
            } else {
                v = ld4(pa + g);
            }
            st2(sdE + row * PE + 2 * col, make_float2(v.x, v.z));
            st2(sdO + row * PE + 2 * col, make_float2(v.y, v.w));
        }
    } else {
        for (int it = tid; it < DT * DC; it += NT) {
            int row = it / DC, col = it - row * DC;
            int gy  = y0 - 4 + row;
            int gx0 = x0 - 4 + 4 * col;
            float4 v;
            if (gy >= 0 && gy < H && gx0 >= 0 && gx0 + 3 < W) {
                size_t g = (size_t)gy * W + gx0;
                v = ld4(sa + g);
                if (DIFF) {
                    float4 w = ld4(sb + g);
                    v.x -= w.x; v.y -= w.y; v.z -= w.z; v.w -= w.w;
                }
            } else {
                int yy = refl(gy, H);
                float t[4];
#pragma unroll
                for (int k = 0; k < 4; k++) {
                    int xx = refl(gx0 + k, W);
                    size_t g = (size_t)yy * W + xx;
                    t[k] = sa[g];
                    if (DIFF) t[k] -= sb[g];
                }
                v = make_float4(t[0], t[1], t[2], t[3]);
            }
            st2(sdE + row * PE + 2 * col, make_float2(v.x, v.z));
            st2(sdO + row * PE + 2 * col, make_float2(v.y, v.w));
        }
    }
    __syncthreads();

    // ---- horizontal gauss (stride-2 folded into parity arrays) ----
    for (int it = tid; it < DT * 9; it += NT) {
        int r = it / 9, k = it - r * 9;
        const float* Er = sdE + r * PE + 4 * k;
        const float* Or = sdO + r * PE + 4 * k;
        float4 Ea = ld4(Er), Eb = ld4(Er + 4);
        float4 Oa = ld4(Or), Ob = ld4(Or + 4);
        float4 o;
        o.x = Ea.x + 6.f*Ea.y + Ea.z + 4.f*(Oa.x + Oa.y);
        o.y = Ea.y + 6.f*Ea.z + Ea.w + 4.f*(Oa.y + Oa.z);
        o.z = Ea.z + 6.f*Ea.w + Eb.x + 4.f*(Oa.z + Oa.w);
        o.w = Ea.w + 6.f*Eb.x + Eb.y + 4.f*(Oa.w + Ob.x);
        st4(st + r * HP + 4 * k, o);
    }
    __syncthreads();

    // ---- vertical gauss, stride 2 ----
    for (int it = tid; it < HT * 9; it += NT) {
        int r = it / 9, ck = it - r * 9;
        const float* base = st + (2 * r) * HP + 4 * ck;
        float4 r0v = ld4(base),        r1v = ld4(base + HP),
               r2v = ld4(base + 2*HP), r3v = ld4(base + 3*HP),
               r4v = ld4(base + 4*HP);
        float4 o;
        o.x = (r0v.x + 4.f*r1v.x + 6.f*r2v.x + 4.f*r3v.x + r4v.x) * (1.f/256.f);
        o.y = (r0v.y + 4.f*r1v.y + 6.f*r2v.y + 4.f*r3v.y + r4v.y) * (1.f/256.f);
        o.z = (r0v.z + 4.f*r1v.z + 6.f*r2v.z + 4.f*r3v.z + r4v.z) * (1.f/256.f);
        o.w = (r0v.w + 4.f*r1v.w + 6.f*r2v.w + 4.f*r3v.w + r4v.w) * (1.f/256.f);
        st4(sdn + r * HP + 4 * ck, o);
    }
    __syncthreads();

    // ---- write interior down tile (next level source) ----
    {
        float* gdn = g_scratch + dstOff + (size_t)bc * h * h;
        for (int it = tid; it < HI * 8; it += NT) {
            int r = it >> 3, ck = it & 7;
            const float* s = sdn + (r + 1) * HP + 4 * ck + 1;
            st4(gdn + (size_t)(r0 + r) * h + c0 + 4 * ck,
                make_float4(s[0], s[1], s[2], s[3]));
        }
    }

    // ---- direct 2D upsample from sdn + |d - up| ----
    float lsum = 0.0f;
    {
        const int r = tid >> 4;       // 0..31
        const int j = tid & 15;       // 0..15
        const float* base = sdn + r * HP + 2 * j;
        float2 A0 = ld2(base),          B0 = ld2(base + 2);
        float2 A1 = ld2(base + HP),     B1 = ld2(base + HP + 2);
        float2 A2 = ld2(base + 2*HP),   B2 = ld2(base + 2*HP + 2);

        float h0A = A0.x + 6.f*A0.y + B0.x, h0B = A0.y + 6.f*B0.x + B0.y;
        float h0C = 4.f*(A0.y + B0.x),      h0D = 4.f*(B0.x + B0.y);
        float h1A = A1.x + 6.f*A1.y + B1.x, h1B = A1.y + 6.f*B1.x + B1.y;
        float h1C = 4.f*(A1.y + B1.x),      h1D = 4.f*(B1.x + B1.y);
        float h2A = A2.x + 6.f*A2.y + B2.x, h2B = A2.y + 6.f*B2.x + B2.y;
        float h2C = 4.f*(A2.y + B2.x),      h2D = 4.f*(B2.x + B2.y);

        constexpr float i64 = 1.f / 64.f;
        float u00 = (h0A + 6.f*h1A + h2A) * i64;
        float u01 = (h0C + 6.f*h1C + h2C) * i64;
        float u02 = (h0B + 6.f*h1B + h2B) * i64;
        float u03 = (h0D + 6.f*h1D + h2D) * i64;
        float u10 = (h1A + h2A) * (4.f * i64);
        float u11 = (h1C + h2C) * (4.f * i64);
        float u12 = (h1B + h2B) * (4.f * i64);
        float u13 = (h1D + h2D) * (4.f * i64);

        const int offE = (2*r + 4) * PE + 2 * j + 2;
        float2 dE0 = ld2(sdE + offE),      dO0 = ld2(sdO + offE);
        float2 dE1 = ld2(sdE + offE + PE), dO1 = ld2(sdO + offE + PE);

        lsum += fabsf(dE0.x - u00) + fabsf(dO0.x - u01)
              + fabsf(dE0.y - u02) + fabsf(dO0.y - u03)
              + fabsf(dE1.x - u10) + fabsf(dO1.x - u11)
              + fabsf(dE1.y - u12) + fabsf(dO1.y - u13);
    }
    block_reduce_atomic(lsum, lvl, sred);
}

// -------- fused levels 3+4 + final reduction: one block per bc-plane --------
// Phase-minimal: hgauss/vgauss with interior fast path, direct 2D upsample
// (no sup round-trip), lvl3-vup merged with lvl4-hgauss, one combined reduce.
__global__ __launch_bounds__(512)
void tail_kernel(int srcOff, float* __restrict__ out)
{
    __shared__ __align__(16) float sa  [64 * 64];   // level-3 source plane
    __shared__ __align__(16) float st3 [64 * 34];
    __shared__ __align__(16) float sdn3[34 * 34];   // lvl3 down (+halo) = lvl4 src
    __shared__ __align__(16) float st4m[32 * 18];
    __shared__ __align__(16) float sdn4[18 * 18];
    __shared__ float sred3[16];
    __shared__ float sred4[16];

    const int tid = threadIdx.x;
    constexpr int NT = 512;
    const int bc = blockIdx.x;

    // ---- load lvl3 plane ----
    const float* g = g_scratch + srcOff + (size_t)bc * 64 * 64;
    for (int idx = tid; idx < 64 * 64 / 4; idx += NT)
        st4(sa + 4*idx, ld4(g + 4*idx));
    __syncthreads();

    // ---- lvl3 hgauss: st3[y][dc], y 0..63, dc 0..33 (down col dc-1) ----
    for (int idx = tid; idx < 64 * 34; idx += NT) {
        int y = idx / 34, dc = idx - y * 34;
        const float* row = sa + y * 64;
        float acc;
        if (dc >= 2 && dc <= 31) {
            const float* p = row + 2*dc - 4;
            acc = p[0] + 4.f*p[1] + 6.f*p[2] + 4.f*p[3] + p[4];
        } else {
            acc = 0.f;
#pragma unroll
            for (int j = 0; j < 5; j++) acc += wt(j) * row[refl(2*dc - 4 + j, 64)];
        }
        st3[idx] = acc;
    }
    __syncthreads();

    // ---- lvl3 vgauss: sdn3[dr][dc], dr 0..33 ----
    for (int idx = tid; idx < 34 * 34; idx += NT) {
        int dr = idx / 34, dc = idx - dr * 34;
        float acc;
        if (dr >= 2 && dr <= 31) {
            const float* p = st3 + (2*dr - 4) * 34 + dc;
            acc = p[0] + 4.f*p[34] + 6.f*p[68] + 4.f*p[102] + p[136];
        } else {
            acc = 0.f;
#pragma unroll
            for (int i = 0; i < 5; i++) acc += wt(i) * st3[refl(2*dr - 4 + i, 64) * 34 + dc];
        }
        sdn3[idx] = acc * (1.f/256.f);
    }
    __syncthreads();

    // ---- phase: lvl3 direct vup (reads sa,sdn3) + lvl4 hgauss (reads sdn3) ----
    float l3 = 0.f;
    {
        const int r = tid >> 4;       // 0..31 row-pair
        const int j = tid & 15;       // 0..15 x-quad
        const float* base = sdn3 + r * 34 + 2 * j;
        float2 A0 = ld2(base),        B0 = ld2(base + 2);
        float2 A1 = ld2(base + 34),   B1 = ld2(base + 36);
        float2 A2 = ld2(base + 68),   B2 = ld2(base + 70);

        float h0A = A0.x + 6.f*A0.y + B0.x, h0B = A0.y + 6.f*B0.x + B0.y;
        float h0C = 4.f*(A0.y + B0.x),      h0D = 4.f*(B0.x + B0.y);
        float h1A = A1.x + 6.f*A1.y + B1.x, h1B = A1.y + 6.f*B1.x + B1.y;
        float h1C = 4.f*(A1.y + B1.x),      h1D = 4.f*(B1.x + B1.y);
        float h2A = A2.x + 6.f*A2.y + B2.x, h2B = A2.y + 6.f*B2.x + B2.y;
        float h2C = 4.f*(A2.y + B2.x),      h2D = 4.f*(B2.x + B2.y);

        constexpr float i64 = 1.f / 64.f;
        float4 d0 = ld4(sa + (2*r) * 64 + 4*j);
        float4 d1 = ld4(sa + (2*r + 1) * 64 + 4*j);
        l3 += fabsf(d0.x - (h0A + 6.f*h1A + h2A) * i64)
            + fabsf(d0.y - (h0C + 6.f*h1C + h2C) * i64)
            + fabsf(d0.z - (h0B + 6.f*h1B + h2B) * i64)
            + fabsf(d0.w - (h0D + 6.f*h1D + h2D) * i64)
            + fabsf(d1.x - (h1A + h2A) * (4.f*i64))
            + fabsf(d1.y - (h1C + h2C) * (4.f*i64))
            + fabsf(d1.z - (h1B + h2B) * (4.f*i64))
            + fabsf(d1.w - (h1D + h2D) * (4.f*i64));
    }
    // lvl4 hgauss: src = sdn3 interior (offset 35, stride 34), H=32
    for (int idx = tid; idx < 32 * 18; idx += NT) {
        int y = idx / 18, dc = idx - y * 18;
        const float* row = sdn3 + 35 + y * 34;
        float acc;
        if (dc >= 2 && dc <= 15) {
            const float* p = row + 2*dc - 4;
            acc = p[0] + 4.f*p[1] + 6.f*p[2] + 4.f*p[3] + p[4];
        } else {
            acc = 0.f;
#pragma unroll
            for (int j = 0; j < 5; j++) acc += wt(j) * row[refl(2*dc - 4 + j, 32)];
        }
        st4m[idx] = acc;
    }
    __syncthreads();

    // ---- lvl4 vgauss ----
    for (int idx = tid; idx < 18 * 18; idx += NT) {
        int dr = idx / 18, dc = idx - dr * 18;
        float acc;
        if (dr >= 2 && dr <= 15) {
            const float* p = st4m + (2*dr - 4) * 18 + dc;
            acc = p[0] + 4.f*p[18] + 6.f*p[36] + 4.f*p[54] + p[72];
        } else {
            acc = 0.f;
#pragma unroll
            for (int i = 0; i < 5; i++) acc += wt(i) * st4m[refl(2*dr - 4 + i, 32) * 18 + dc];
        }
        sdn4[idx] = acc * (1.f/256.f);
    }
    __syncthreads();

    // ---- lvl4 direct vup (threads 0..127) ----
    float l4 = 0.f;
    if (tid < 16 * 8) {
        const int r = tid >> 3;       // 0..15 row-pair
        const int j = tid & 7;        // 0..7 x-quad
        const float* base = sdn4 + r * 18 + 2 * j;
        float2 A0 = ld2(base),        B0 = ld2(base + 2);
        float2 A1 = ld2(base + 18),   B1 = ld2(base + 20);
        float2 A2 = ld2(base + 36),   B2 = ld2(base + 38);

        float h0A = A0.x + 6.f*A0.y + B0.x, h0B = A0.y + 6.f*B0.x + B0.y;
        float h0C = 4.f*(A0.y + B0.x),      h0D = 4.f*(B0.x + B0.y);
        float h1A = A1.x + 6.f*A1.y + B1.x, h1B = A1.y + 6.f*B1.x + B1.y;
        float h1C = 4.f*(A1.y + B1.x),      h1D = 4.f*(B1.x + B1.y);
        float h2A = A2.x + 6.f*A2.y + B2.x, h2B = A2.y + 6.f*B2.x + B2.y;
        float h2C = 4.f*(A2.y + B2.x),      h2D = 4.f*(B2.x + B2.y);

        constexpr float i64 = 1.f / 64.f;
        const float* s0 = sdn3 + 35 + (2*r) * 34 + 4*j;       // lvl4 source rows
        const float* s1 = s0 + 34;
        l4 += fabsf(s0[0] - (h0A + 6.f*h1A + h2A) * i64)
            + fabsf(s0[1] - (h0C + 6.f*h1C + h2C) * i64)
            + fabsf(s0[2] - (h0B + 6.f*h1B + h2B) * i64)
            + fabsf(s0[3] - (h0D + 6.f*h1D + h2D) * i64)
            + fabsf(s1[0] - (h1A + h2A) * (4.f*i64))
            + fabsf(s1[1] - (h1C + h2C) * (4.f*i64))
            + fabsf(s1[2] - (h1B + h2B) * (4.f*i64))
            + fabsf(s1[3] - (h1D + h2D) * (4.f*i64));
    }

    // ---- combined block reduce for (l3, l4): one smem round ----
#pragma unroll
    for (int o = 16; o; o >>= 1) {
        l3 += __shfl_down_sync(0xffffffffu, l3, o);
        l4 += __shfl_down_sync(0xffffffffu, l4, o);
    }
    if ((tid & 31) == 0) { sred3[tid >> 5] = l3; sred4[tid >> 5] = l4; }
    __syncthreads();
    if (tid < 16) {
        float x3 = sred3[tid], x4 = sred4[tid];
#pragma unroll
        for (int o = 8; o; o >>= 1) {
            x3 += __shfl_down_sync(0xffffu, x3, o);
            x4 += __shfl_down_sync(0xffffu, x4, o);
        }
        if (tid == 0) {
            atomicAdd(&g_sums[3], (double)x3);
            atomicAdd(&g_sums[4], (double)x4);
        }
    }
    __syncthreads();

    // ---- last block finalizes ----
    if (tid == 0) {
        __threadfence();
        unsigned int t = atomicAdd(&g_ticket, 1u);
        if (t == gridDim.x - 1) {
            const double inv[NLVL] = {
                1.0 / ((double)BC * 512 * 512),
                1.0 / ((double)BC * 256 * 256),
                1.0 / ((double)BC * 128 * 128),
                1.0 / ((double)BC *  64 *  64),
                1.0 / ((double)BC *  32 *  32)
            };
            double tot = 0.0;
#pragma unroll
            for (int l = 0; l < NLVL; l++) tot += g_sums[l] * inv[l];
            out[0] = (float)tot;
#pragma unroll
            for (int l = 0; l < NLVL; l++) g_sums[l] = 0.0;
            g_ticket = 0;
            __threadfence();
        }
    }
}

extern "C" void kernel_launch(void* const* d_in, const int* in_sizes, int n_in,
                              void* d_out, int out_size) {
    const float* input  = (const float*)d_in[0];
    const float* target = (const float*)d_in[1];
    float* out = (float*)d_out;

    const int OFF0 = 0;
    const int OFF1 = BC * 256*256;
    const int OFF2 = OFF1 + BC * 128*128;

    lvl_kernel<true ><<<dim3(64, BC), 512>>>(input,  target,  0,    OFF0, 512, 0, 8);
    lvl_kernel<false><<<dim3(16, BC), 512>>>(nullptr, nullptr, OFF0, OFF1, 256, 1, 4);
    lvl_kernel<false><<<dim3(4,  BC), 512>>>(nullptr, nullptr, OFF1, OFF2, 128, 2, 2);
    tail_kernel<<<BC, 512>>>(OFF2, out);
}